// round 11
// baseline (speedup 1.0000x reference)
#include <cuda_runtime.h>
#include <cstdint>

// z_e: [32,64,64,64] fp32 -> N=131072 rows, D=64; codebook: [512,64] fp32
// out: z_q (N*D fp32, raw reshape) then indices (N as fp32)
#define NROWS   131072
#define DDIM    64
#define KCB     512
#define TILE_M  128
#define NTILES  (NROWS / TILE_M)    // 1024
#define NCTAS   148
#define TPB     128
#define STR     68                  // padded smem stride (floats) -> conflict-free
#define EPS     2e-4f               // rescue margin (proven R10: 0 escapes)

// SMEM layout (float indices)
#define F_AHI   0
#define F_BHI   (F_AHI + TILE_M * STR)     // 8704
#define F_EN    (F_BHI + KCB * STR)        // 43520
#define F_XN    (F_EN + KCB)               // 44032
#define F_D1    (F_XN + TILE_M)            // 44160
#define F_D2    (F_D1 + TILE_M)            // 44288
#define F_K1    (F_D2 + TILE_M)            // 44416
#define SMEM_FLOATS (F_K1 + TILE_M)        // 44544
#define SMEM_BYTES  (SMEM_FLOATS * 4)      // 178176 B

__device__ unsigned char g_flag[NROWS];    // per-row rescue flag, rewritten every run

__device__ __forceinline__ uint32_t f2tf32(float v) {
    uint32_t r; asm("cvt.rna.tf32.f32 %0, %1;" : "=r"(r) : "f"(v)); return r;
}
__device__ __forceinline__ void mma_tf32(float* c, const uint32_t* a,
                                         uint32_t b0, uint32_t b1) {
    asm volatile(
        "mma.sync.aligned.m16n8k8.row.col.f32.tf32.tf32.f32 "
        "{%0,%1,%2,%3}, {%4,%5,%6,%7}, {%8,%9}, {%0,%1,%2,%3};"
        : "+f"(c[0]), "+f"(c[1]), "+f"(c[2]), "+f"(c[3])
        : "r"(a[0]), "r"(a[1]), "r"(a[2]), "r"(a[3]), "r"(b0), "r"(b1));
}

// SACRED: XLA row-reduction tree for sum of squares over 64 f32 (proven R4/R6).
__device__ __forceinline__ float xla_row_sumsq(const float* __restrict__ x)
{
    float t[32];
    #pragma unroll
    for (int l = 0; l < 32; ++l)
        t[l] = __fadd_rn(__fmul_rn(x[2 * l], x[2 * l]),
                         __fmul_rn(x[2 * l + 1], x[2 * l + 1]));
    #pragma unroll
    for (int off = 16; off >= 1; off >>= 1)
        #pragma unroll
        for (int l = 0; l < off; ++l)
            t[l] = __fadd_rn(t[l], t[l + off]);
    return t[0];
}

__global__ __launch_bounds__(TPB, 1)
void vq_mma(const float* __restrict__ z_e,
            const float* __restrict__ cb,
            float* __restrict__ out,
            int write_idx)
{
    extern __shared__ float smf[];
    uint32_t* smu = (uint32_t*)smf;
    int* smk = (int*)(smf + F_K1);
    const int tid  = threadIdx.x;
    const int wid  = tid >> 5;
    const int lane = tid & 31;
    const int g = lane >> 2;
    const int q = lane & 3;
    const int mb = wid * 32;

    // ---- stage B: all 512 codewords as tf32 + SACRED en ----
    for (int i = tid; i < KCB * DDIM; i += TPB) {
        const int n = i >> 6, k = i & 63;
        smu[F_BHI + n * STR + k] = f2tf32(cb[i]);
    }
    for (int n = tid; n < KCB; n += TPB)
        smf[F_EN + n] = xla_row_sumsq(cb + n * DDIM);
    __syncthreads();

    for (int t = blockIdx.x; t < NTILES; t += NCTAS) {
        const int row = t * TILE_M + tid;
        // ---- stage A (NCHW gather) + SACRED xn + tf32 ----
        {
            float x[DDIM];
            const long long base = (long long)(row >> 12) * 262144 + (row & 4095);
            #pragma unroll
            for (int c = 0; c < DDIM; ++c)
                x[c] = z_e[base + (long long)c * 4096];
            smf[F_XN + tid] = xla_row_sumsq(x);
            #pragma unroll
            for (int c = 0; c < DDIM; ++c)
                smu[F_AHI + tid * STR + c] = f2tf32(x[c]);
        }
        __syncthreads();

        // ---- load the warp's A tile as MMA fragments, held in regs ----
        // afr[kb][0..3] = m-block rows mb+g, mb+g+8;  [4..7] = rows +16, +24
        uint32_t afr[8][8];
        #pragma unroll
        for (int kb = 0; kb < 8; ++kb) {
            const uint32_t* A0 = smu + F_AHI + (mb + g) * STR + kb * 8 + q;
            afr[kb][0] = A0[0];
            afr[kb][1] = A0[8 * STR];
            afr[kb][2] = A0[4];
            afr[kb][3] = A0[8 * STR + 4];
            const uint32_t* A1 = A0 + 16 * STR;
            afr[kb][4] = A1[0];
            afr[kb][5] = A1[8 * STR];
            afr[kb][6] = A1[4];
            afr[kb][7] = A1[8 * STR + 4];
        }

        float d1[4] = {3.4e38f, 3.4e38f, 3.4e38f, 3.4e38f};
        float d2[4] = {3.4e38f, 3.4e38f, 3.4e38f, 3.4e38f};
        int   k1[4] = {0, 0, 0, 0};
        float xnr[4];
        #pragma unroll
        for (int ri = 0; ri < 4; ++ri)
            xnr[ri] = smf[F_XN + mb + g + ri * 8];

        #pragma unroll 1
        for (int ng = 0; ng < 16; ++ng) {          // 32 cols per group
            float acc[2][4][4];
            #pragma unroll
            for (int m = 0; m < 2; ++m)
                #pragma unroll
                for (int s = 0; s < 4; ++s)
                    #pragma unroll
                    for (int c = 0; c < 4; ++c) acc[m][s][c] = 0.f;

            #pragma unroll
            for (int kb = 0; kb < 8; ++kb) {
                #pragma unroll
                for (int s = 0; s < 4; ++s) {
                    const int n0 = ng * 32 + s * 8;
                    const uint32_t* Bp = smu + F_BHI + (n0 + g) * STR + kb * 8 + q;
                    const uint32_t b0 = Bp[0], b1 = Bp[4];
                    mma_tf32(acc[0][s], &afr[kb][0], b0, b1);
                    mma_tf32(acc[1][s], &afr[kb][4], b0, b1);
                }
            }
            // ---- epilogue: filter dist + (d1,k1,d2), ascending k ----
            #pragma unroll
            for (int s = 0; s < 4; ++s) {
                const int c0 = ng * 32 + s * 8 + 2 * q;
                const float en0 = smf[F_EN + c0];
                const float en1 = smf[F_EN + c0 + 1];
                #pragma unroll
                for (int rg = 0; rg < 2; ++rg) {
                    #pragma unroll
                    for (int hr = 0; hr < 2; ++hr) {
                        const int ri = rg * 2 + hr;
                        const float dd0 = __fsub_rn(__fadd_rn(xnr[ri], en0),
                                                    __fmul_rn(2.f, acc[rg][s][hr * 2 + 0]));
                        const float dd1 = __fsub_rn(__fadd_rn(xnr[ri], en1),
                                                    __fmul_rn(2.f, acc[rg][s][hr * 2 + 1]));
                        if (dd0 < d1[ri]) { d2[ri] = d1[ri]; d1[ri] = dd0; k1[ri] = c0; }
                        else if (dd0 < d2[ri]) d2[ri] = dd0;
                        if (dd1 < d1[ri]) { d2[ri] = d1[ri]; d1[ri] = dd1; k1[ri] = c0 + 1; }
                        else if (dd1 < d2[ri]) d2[ri] = dd1;
                    }
                }
            }
        }

        // quad merge of (d1,k1,d2): lexicographic best; union second-best
        #pragma unroll
        for (int ri = 0; ri < 4; ++ri) {
            float a = d1[ri], b = d2[ri]; int i = k1[ri];
            #pragma unroll
            for (int off = 1; off <= 2; off <<= 1) {
                const float oa = __shfl_xor_sync(0xffffffffu, a, off);
                const float ob = __shfl_xor_sync(0xffffffffu, b, off);
                const int   oi = __shfl_xor_sync(0xffffffffu, i, off);
                const float hi = fmaxf(a, oa);
                b = fminf(fminf(b, ob), hi);
                if (oa < a || (oa == a && oi < i)) { a = oa; i = oi; }
            }
            d1[ri] = a; d2[ri] = b; k1[ri] = i;
        }
        if (q == 0) {
            #pragma unroll
            for (int ri = 0; ri < 4; ++ri) {
                const int lr = mb + g + ri * 8;
                smf[F_D1 + lr] = d1[ri];
                smf[F_D2 + lr] = d2[ri];
                smk[lr] = k1[ri];
            }
        }
        __syncthreads();

        // outputs + unconditional per-row rescue flag (thread tid owns row tid)
        {
            const float a = smf[F_D1 + tid];
            const float b = smf[F_D2 + tid];
            const int   bi = smk[tid];
            const float4* src = (const float4*)(cb + (size_t)bi * DDIM);
            float4* o = (float4*)(out + (size_t)row * DDIM);
            #pragma unroll
            for (int j = 0; j < DDIM / 4; ++j) o[j] = src[j];
            if (write_idx) out[(size_t)NROWS * DDIM + row] = (float)bi;
            g_flag[row] = (b - a <= EPS) ? 1 : 0;
        }
        __syncthreads();   // before next tile overwrites A/XN/results
    }
}

// Exact scalar rescue — bitwise the proven R6 path, for flagged rows only.
__global__ __launch_bounds__(256, 1)
void vq_rescue(const float* __restrict__ z_e,
               const float* __restrict__ cb,
               float* __restrict__ out,
               int write_idx)
{
    const int lane = threadIdx.x & 31;
    const int w    = (blockIdx.x * blockDim.x + threadIdx.x) >> 5;  // 4096 warps
    const int base_row = w * 32;

    unsigned mask = __ballot_sync(0xffffffffu, g_flag[base_row + lane] != 0);
    while (mask) {
        const int r = __ffs(mask) - 1;
        mask &= mask - 1;
        const int row = base_row + r;

        float x[DDIM];
        const long long base = (long long)(row >> 12) * 262144 + (row & 4095);
        #pragma unroll
        for (int c = 0; c < DDIM; ++c)
            x[c] = z_e[base + (long long)c * 4096];
        const float xn = xla_row_sumsq(x);   // SACRED

        float best = 3.402823466e38f;
        int   bi   = KCB;
        for (int k = lane; k < KCB; k += 32) {
            const float* e = cb + (size_t)k * DDIM;
            const float en = xla_row_sumsq(e);   // SACRED
            float p0 = 0.f, p1 = 0.f, p2 = 0.f, p3 = 0.f;
            #pragma unroll
            for (int j = 0; j < DDIM / 4; ++j) {
                p0 = fmaf(x[4 * j + 0], e[4 * j + 0], p0);
                p1 = fmaf(x[4 * j + 1], e[4 * j + 1], p1);
                p2 = fmaf(x[4 * j + 2], e[4 * j + 2], p2);
                p3 = fmaf(x[4 * j + 3], e[4 * j + 3], p3);
            }
            const float dot = (p0 + p1) + (p2 + p3);   // proven-free order
            // SACRED final rounding
            const float d = __fsub_rn(__fadd_rn(xn, en), __fmul_rn(2.f, dot));
            if (d < best) { best = d; bi = k; }        // ascending k, strict <
        }
        // lexicographic (d, k) merge -> first-index tie semantics
        #pragma unroll
        for (int off = 16; off >= 1; off >>= 1) {
            const float od = __shfl_xor_sync(0xffffffffu, best, off);
            const int   oi = __shfl_xor_sync(0xffffffffu, bi, off);
            if (od < best || (od == best && oi < bi)) { best = od; bi = oi; }
        }
        const float4* src = (const float4*)(cb + (size_t)bi * DDIM);
        if (lane < DDIM / 4)
            ((float4*)(out + (size_t)row * DDIM))[lane] = src[lane];
        if (write_idx && lane == 0)
            out[(size_t)NROWS * DDIM + row] = (float)bi;
    }
}

extern "C" void kernel_launch(void* const* d_in, const int* in_sizes, int n_in,
                              void* d_out, int out_size)
{
    const float* z_e = (const float*)d_in[0];
    const float* cb  = (const float*)d_in[1];
    if (n_in >= 2 && in_sizes[0] == KCB * DDIM && in_sizes[1] == NROWS * DDIM) {
        const float* t = z_e; z_e = cb; cb = t;   // defensive input-order swap
    }
    const int write_idx = (out_size >= NROWS * DDIM + NROWS) ? 1 : 0;

    cudaFuncSetAttribute(vq_mma, cudaFuncAttributeMaxDynamicSharedMemorySize,
                         SMEM_BYTES);
    vq_mma<<<NCTAS, TPB, SMEM_BYTES>>>(z_e, cb, (float*)d_out, write_idx);
    vq_rescue<<<(NROWS / 32) / 8, 256>>>(z_e, cb, (float*)d_out, write_idx);
}

// round 12
// speedup vs baseline: 4.3840x; 4.3840x over previous
#include <cuda_runtime.h>
#include <cstdint>

// z_e: [32,64,64,64] fp32 -> N=131072 rows, D=64; codebook: [512,64] fp32
// out: z_q (N*D fp32, raw reshape) then indices (N as fp32)
#define NROWS   131072
#define DDIM    64
#define KCB     512
#define TILE_M  128
#define NTILES  (NROWS / TILE_M)    // 1024
#define NCTAS   148
#define TPB     256
#define STR     68                  // padded smem stride (floats) -> conflict-free frags
#define EPS     2e-4f               // rescue margin (proven R10/R11: 0 escapes)

// vq_mma SMEM layout (float indices)
#define F_AHI   0
#define F_BHI   (F_AHI + TILE_M * STR)     // 8704
#define F_EN    (F_BHI + KCB * STR)        // 43520
#define F_XN    (F_EN + KCB)               // 44032
#define F_D1    (F_XN + TILE_M)            // 44160  (2 halves x 128)
#define F_D2    (F_D1 + 2 * TILE_M)        // 44416
#define F_K1    (F_D2 + 2 * TILE_M)        // 44672
#define SMEM_FLOATS (F_K1 + 2 * TILE_M)    // 44928
#define SMEM_BYTES  (SMEM_FLOATS * 4)      // 179712 B

// rescue SMEM
#define R_STR   65                          // lane k -> bank k (conflict-free)
#define R_EN    (KCB * R_STR)               // 33280
#define R_FLOATS (R_EN + KCB)               // 33792
#define R_BYTES  (R_FLOATS * 4)             // 135168 B

__device__ unsigned char g_flag[NROWS];     // per-row rescue flag, rewritten every run

__device__ __forceinline__ uint32_t f2tf32(float v) {
    uint32_t r; asm("cvt.rna.tf32.f32 %0, %1;" : "=r"(r) : "f"(v)); return r;
}
__device__ __forceinline__ void mma_tf32(float* c, const uint32_t* a,
                                         uint32_t b0, uint32_t b1) {
    asm volatile(
        "mma.sync.aligned.m16n8k8.row.col.f32.tf32.tf32.f32 "
        "{%0,%1,%2,%3}, {%4,%5,%6,%7}, {%8,%9}, {%0,%1,%2,%3};"
        : "+f"(c[0]), "+f"(c[1]), "+f"(c[2]), "+f"(c[3])
        : "r"(a[0]), "r"(a[1]), "r"(a[2]), "r"(a[3]), "r"(b0), "r"(b1));
}

// SACRED: XLA row-reduction tree for sum of squares over 64 f32 (proven R4/R6).
__device__ __forceinline__ float xla_row_sumsq(const float* __restrict__ x)
{
    float t[32];
    #pragma unroll
    for (int l = 0; l < 32; ++l)
        t[l] = __fadd_rn(__fmul_rn(x[2 * l], x[2 * l]),
                         __fmul_rn(x[2 * l + 1], x[2 * l + 1]));
    #pragma unroll
    for (int off = 16; off >= 1; off >>= 1)
        #pragma unroll
        for (int l = 0; l < off; ++l)
            t[l] = __fadd_rn(t[l], t[l + off]);
    return t[0];
}

__global__ __launch_bounds__(TPB, 1)
void vq_mma(const float* __restrict__ z_e,
            const float* __restrict__ cb,
            float* __restrict__ out,
            int write_idx)
{
    extern __shared__ float smf[];
    uint32_t* smu = (uint32_t*)smf;
    int* smk = (int*)(smf + F_K1);
    const int tid  = threadIdx.x;
    const int wid  = tid >> 5;
    const int lane = tid & 31;
    const int g = lane >> 2;
    const int q = lane & 3;
    const int half  = wid >> 2;         // 0: cols 0..255, 1: cols 256..511
    const int mb    = (wid & 3) * 32;   // warp's 32-row block
    const int nbase = half * 256;

    // ---- stage B: all 512 codewords as tf32 + SACRED en ----
    for (int i = tid; i < KCB * DDIM; i += TPB) {
        const int n = i >> 6, k = i & 63;
        smu[F_BHI + n * STR + k] = f2tf32(cb[i]);
    }
    for (int n = tid; n < KCB; n += TPB)
        smf[F_EN + n] = xla_row_sumsq(cb + n * DDIM);
    __syncthreads();

    for (int t = blockIdx.x; t < NTILES; t += NCTAS) {
        const int rbase = t * TILE_M;
        // ---- stage A fp32 (coalesced: tile never straddles a 4096 block) ----
        {
            const long long gb = (long long)(rbase >> 12) * 262144 + (rbase & 4095);
            for (int i = tid; i < TILE_M * DDIM; i += TPB) {
                const int c = i >> 7, r = i & 127;
                smf[F_AHI + r * STR + c] = z_e[gb + (long long)c * 4096 + r];
            }
        }
        __syncthreads();
        // SACRED xn per row
        if (tid < TILE_M)
            smf[F_XN + tid] = xla_row_sumsq(smf + F_AHI + tid * STR);
        __syncthreads();
        // convert A in place to tf32
        for (int i = tid; i < TILE_M * DDIM; i += TPB) {
            const int c = i >> 7, r = i & 127;
            const float v = smf[F_AHI + r * STR + c];
            smu[F_AHI + r * STR + c] = f2tf32(v);
        }
        __syncthreads();

        // ---- warp's A tile as MMA fragments, held in regs ----
        uint32_t afr[8][8];
        #pragma unroll
        for (int kb = 0; kb < 8; ++kb) {
            const uint32_t* A0 = smu + F_AHI + (mb + g) * STR + kb * 8 + q;
            afr[kb][0] = A0[0];            afr[kb][1] = A0[8 * STR];
            afr[kb][2] = A0[4];            afr[kb][3] = A0[8 * STR + 4];
            const uint32_t* A1 = A0 + 16 * STR;
            afr[kb][4] = A1[0];            afr[kb][5] = A1[8 * STR];
            afr[kb][6] = A1[4];            afr[kb][7] = A1[8 * STR + 4];
        }

        float d1[4] = {3.4e38f, 3.4e38f, 3.4e38f, 3.4e38f};
        float d2[4] = {3.4e38f, 3.4e38f, 3.4e38f, 3.4e38f};
        int   k1[4] = {0, 0, 0, 0};
        float xnr[4];
        #pragma unroll
        for (int ri = 0; ri < 4; ++ri)
            xnr[ri] = smf[F_XN + mb + g + ri * 8];

        #pragma unroll 1
        for (int ng = 0; ng < 8; ++ng) {           // 32 cols/group, warp's half
            float acc[2][4][4];
            #pragma unroll
            for (int m = 0; m < 2; ++m)
                #pragma unroll
                for (int s = 0; s < 4; ++s)
                    #pragma unroll
                    for (int c = 0; c < 4; ++c) acc[m][s][c] = 0.f;

            #pragma unroll
            for (int kb = 0; kb < 8; ++kb) {
                #pragma unroll
                for (int s = 0; s < 4; ++s) {
                    const int n0 = nbase + ng * 32 + s * 8;
                    const uint32_t* Bp = smu + F_BHI + (n0 + g) * STR + kb * 8 + q;
                    const uint32_t b0 = Bp[0], b1 = Bp[4];
                    mma_tf32(acc[0][s], &afr[kb][0], b0, b1);
                    mma_tf32(acc[1][s], &afr[kb][4], b0, b1);
                }
            }
            // filter dist + (d1,k1,d2), ascending k within the half
            #pragma unroll
            for (int s = 0; s < 4; ++s) {
                const int c0 = nbase + ng * 32 + s * 8 + 2 * q;
                const float en0 = smf[F_EN + c0];
                const float en1 = smf[F_EN + c0 + 1];
                #pragma unroll
                for (int rg = 0; rg < 2; ++rg) {
                    #pragma unroll
                    for (int hr = 0; hr < 2; ++hr) {
                        const int ri = rg * 2 + hr;
                        const float dd0 = __fsub_rn(__fadd_rn(xnr[ri], en0),
                                                    __fmul_rn(2.f, acc[rg][s][hr * 2 + 0]));
                        const float dd1 = __fsub_rn(__fadd_rn(xnr[ri], en1),
                                                    __fmul_rn(2.f, acc[rg][s][hr * 2 + 1]));
                        if (dd0 < d1[ri]) { d2[ri] = d1[ri]; d1[ri] = dd0; k1[ri] = c0; }
                        else if (dd0 < d2[ri]) d2[ri] = dd0;
                        if (dd1 < d1[ri]) { d2[ri] = d1[ri]; d1[ri] = dd1; k1[ri] = c0 + 1; }
                        else if (dd1 < d2[ri]) d2[ri] = dd1;
                    }
                }
            }
        }

        // quad merge: lexicographic best; union second-best
        #pragma unroll
        for (int ri = 0; ri < 4; ++ri) {
            float a = d1[ri], b = d2[ri]; int i = k1[ri];
            #pragma unroll
            for (int off = 1; off <= 2; off <<= 1) {
                const float oa = __shfl_xor_sync(0xffffffffu, a, off);
                const float ob = __shfl_xor_sync(0xffffffffu, b, off);
                const int   oi = __shfl_xor_sync(0xffffffffu, i, off);
                const float hi = fmaxf(a, oa);
                b = fminf(fminf(b, ob), hi);
                if (oa < a || (oa == a && oi < i)) { a = oa; i = oi; }
            }
            d1[ri] = a; d2[ri] = b; k1[ri] = i;
        }
        if (q == 0) {
            #pragma unroll
            for (int ri = 0; ri < 4; ++ri) {
                const int lr = half * TILE_M + mb + g + ri * 8;
                smf[F_D1 + lr] = d1[ri];
                smf[F_D2 + lr] = d2[ri];
                smk[lr] = k1[ri];
            }
        }
        __syncthreads();

        // merge halves (half0 wins ties: its k is always lower) + outputs + flag
        if (tid < TILE_M) {
            const float dA = smf[F_D1 + tid],        dB = smf[F_D1 + TILE_M + tid];
            const float sA = smf[F_D2 + tid],        sB = smf[F_D2 + TILE_M + tid];
            const int   kA = smk[tid],               kB = smk[TILE_M + tid];
            float d1f, d2f; int kf;
            if (dA <= dB) { d1f = dA; kf = kA; d2f = fminf(sA, dB); }
            else          { d1f = dB; kf = kB; d2f = fminf(sB, dA); }

            const int row = rbase + tid;
            const float4* src = (const float4*)(cb + (size_t)kf * DDIM);
            float4* o = (float4*)(out + (size_t)row * DDIM);
            #pragma unroll
            for (int j = 0; j < DDIM / 4; ++j) o[j] = src[j];
            if (write_idx) out[(size_t)NROWS * DDIM + row] = (float)kf;
            g_flag[row] = (d2f - d1f <= EPS) ? 1 : 0;
        }
        __syncthreads();   // before next tile overwrites A/XN/results
    }
}

// Exact scalar rescue — bitwise the proven R6 path; codebook staged in SMEM.
__global__ __launch_bounds__(TPB, 1)
void vq_rescue(const float* __restrict__ z_e,
               const float* __restrict__ cb,
               float* __restrict__ out,
               int write_idx)
{
    extern __shared__ float rsm[];
    const int tid  = threadIdx.x;
    const int lane = tid & 31;
    const int wid  = tid >> 5;

    // stage codebook (padded stride 65 -> lane k reads bank k) + SACRED en
    for (int i = tid; i < KCB * DDIM; i += TPB) {
        const int n = i >> 6, c = i & 63;
        rsm[n * R_STR + c] = cb[i];
    }
    __syncthreads();
    for (int n = tid; n < KCB; n += TPB)
        rsm[R_EN + n] = xla_row_sumsq(rsm + n * R_STR);   // SACRED (identical bits)
    __syncthreads();

    const int gw = blockIdx.x * (TPB / 32) + wid;          // global warp id
    const int nw = NCTAS * (TPB / 32);                     // 1184 warps

    for (int strip = gw; strip < NROWS / 32; strip += nw) {
        const int base_row = strip * 32;
        unsigned mask = __ballot_sync(0xffffffffu, g_flag[base_row + lane] != 0);
        while (mask) {
            const int r = __ffs(mask) - 1;
            mask &= mask - 1;
            const int row = base_row + r;

            float x[DDIM];
            const long long base = (long long)(row >> 12) * 262144 + (row & 4095);
            #pragma unroll
            for (int c = 0; c < DDIM; ++c)
                x[c] = z_e[base + (long long)c * 4096];    // broadcast loads
            const float xn = xla_row_sumsq(x);             // SACRED

            float best = 3.402823466e38f;
            int   bi   = KCB;
            for (int k = lane; k < KCB; k += 32) {
                const float* e = rsm + k * R_STR;          // conflict-free LDS
                const float en = rsm[R_EN + k];
                float p0 = 0.f, p1 = 0.f, p2 = 0.f, p3 = 0.f;
                #pragma unroll
                for (int j = 0; j < DDIM / 4; ++j) {
                    p0 = fmaf(x[4 * j + 0], e[4 * j + 0], p0);
                    p1 = fmaf(x[4 * j + 1], e[4 * j + 1], p1);
                    p2 = fmaf(x[4 * j + 2], e[4 * j + 2], p2);
                    p3 = fmaf(x[4 * j + 3], e[4 * j + 3], p3);
                }
                const float dot = (p0 + p1) + (p2 + p3);   // proven-free order
                // SACRED final rounding
                const float d = __fsub_rn(__fadd_rn(xn, en), __fmul_rn(2.f, dot));
                if (d < best) { best = d; bi = k; }        // ascending k, strict <
            }
            // lexicographic (d, k) merge -> first-index tie semantics
            #pragma unroll
            for (int off = 16; off >= 1; off >>= 1) {
                const float od = __shfl_xor_sync(0xffffffffu, best, off);
                const int   oi = __shfl_xor_sync(0xffffffffu, bi, off);
                if (od < best || (od == best && oi < bi)) { best = od; bi = oi; }
            }
            const float4* src = (const float4*)(cb + (size_t)bi * DDIM);
            if (lane < DDIM / 4)
                ((float4*)(out + (size_t)row * DDIM))[lane] = src[lane];
            if (write_idx && lane == 0)
                out[(size_t)NROWS * DDIM + row] = (float)bi;
        }
    }
}

extern "C" void kernel_launch(void* const* d_in, const int* in_sizes, int n_in,
                              void* d_out, int out_size)
{
    const float* z_e = (const float*)d_in[0];
    const float* cb  = (const float*)d_in[1];
    if (n_in >= 2 && in_sizes[0] == KCB * DDIM && in_sizes[1] == NROWS * DDIM) {
        const float* t = z_e; z_e = cb; cb = t;   // defensive input-order swap
    }
    const int write_idx = (out_size >= NROWS * DDIM + NROWS) ? 1 : 0;

    cudaFuncSetAttribute(vq_mma, cudaFuncAttributeMaxDynamicSharedMemorySize,
                         SMEM_BYTES);
    cudaFuncSetAttribute(vq_rescue, cudaFuncAttributeMaxDynamicSharedMemorySize,
                         R_BYTES);
    vq_mma<<<NCTAS, TPB, SMEM_BYTES>>>(z_e, cb, (float*)d_out, write_idx);
    vq_rescue<<<NCTAS, TPB, R_BYTES>>>(z_e, cb, (float*)d_out, write_idx);
}